// round 5
// baseline (speedup 1.0000x reference)
#include <cuda_runtime.h>

// Ordered_GCN: B=64, N=207, K=32, C=8, D_IN=64, D_OUT=64, tokens = 13248.
// R5: barrier-free warp-autonomous design. No cp.async, no __syncthreads.
// Warp w of a CTA owns (class c = w>>1, outputs o = (w&1)*32 + lane) and
// walks tokens t = bid, bid+grid, ...  Per token:
//   - idx row prefetched one token ahead (register)
//   - ballot -> member mask -> LDG.64 only member rows (pair warp L1-hits)
//   - lane accumulates class-sum pair (d = 2*lane, 2*lane+1)
//   - stage pairs in warp-private smem slot, GEMV via 16 broadcast LDS.128
//     against register-resident W row (32 x fma.rn.f32x2), fast tanh, store.

#define KNB   32
#define DIN   64
#define NTHR  512
#define TOKEN_IN  2048   // floats per token
#define TOKEN_OUT 512    // floats per token

typedef unsigned long long u64;

__device__ __forceinline__ u64 ffma2(u64 a, u64 b, u64 c) {
    u64 d;
    asm("fma.rn.f32x2 %0, %1, %2, %3;" : "=l"(d) : "l"(a), "l"(b), "l"(c));
    return d;
}
__device__ __forceinline__ u64 pack_f2(float x, float y) {
    u64 r; asm("mov.b64 %0, {%1, %2};" : "=l"(r) : "f"(x), "f"(y)); return r;
}
__device__ __forceinline__ void unpack_f2(u64 v, float& x, float& y) {
    asm("mov.b64 {%0, %1}, %2;" : "=f"(x), "=f"(y) : "l"(v));
}
__device__ __forceinline__ float fast_tanh(float z) {
    // 1 - 2/(e^{2z}+1): ~1e-7 abs err, saturates correctly
    float e = __expf(2.0f * z);
    return 1.0f - __fdividef(2.0f, e + 1.0f);
}

__global__ void __launch_bounds__(NTHR, 1)
ordered_gcn_kernel(const int* __restrict__ idx,
                   const float* __restrict__ win,
                   const float* __restrict__ W,
                   float* __restrict__ out,
                   int total)
{
    // warp-private staging: 16 warps x 32 f32x2 pairs (16B-aligned rows)
    __shared__ u64 stage[16][32];

    const int tid  = threadIdx.x;
    const int lane = tid & 31;
    const int warp = tid >> 5;
    const int c    = warp >> 1;                 // class (warp-uniform)
    const int o    = ((warp & 1) << 5) | lane;  // output column 0..63

    // ---- W[c][o][0:64] register-resident as 32 packed f32x2 ----
    u64 w[32];
    {
        const float4* gw = (const float4*)(W + ((c * DIN + o) * DIN));
        #pragma unroll
        for (int j = 0; j < 16; j++) {
            float4 v = gw[j];
            w[2*j]   = pack_f2(v.x, v.y);
            w[2*j+1] = pack_f2(v.z, v.w);
        }
    }

    const int grid = gridDim.x;
    int t = blockIdx.x;
    if (t >= total) return;

    // prefetch idx lane-value for first token
    int myidx = __ldg(idx + (size_t)t * KNB + lane);

    u64* slot = stage[warp];
    const size_t out_off = (size_t)(c << 6) + o;

    for (; t < total; t += grid) {
        const int nt = t + grid;

        // membership for current token (idx already in register)
        unsigned mask = __ballot_sync(0xffffffffu, myidx == c);

        // prefetch next token's idx immediately (independent LDG)
        if (nt < total) myidx = __ldg(idx + (size_t)nt * KNB + lane);

        const int cnt = __popc(mask);
        const float rc = __fdividef(1.0f, (float)(cnt > 0 ? cnt : 1));

        // ---- class-sum pair for d = 2*lane, 2*lane+1 (direct gmem reads) ----
        const float2* rows = (const float2*)(win + (size_t)t * TOKEN_IN);
        float s0 = 0.0f, s1 = 0.0f;
        unsigned m = mask;
        while (m) {
            int k = __ffs(m) - 1;
            m &= m - 1;
            float2 v = __ldg(rows + k * 32 + lane);   // 256B/row, coalesced
            s0 += v.x; s1 += v.y;
        }

        __syncwarp();                 // prior GEMV reads of slot complete
        slot[lane] = pack_f2(s0, s1);
        __syncwarp();                 // all pairs staged

        // ---- GEMV: 16 broadcast LDS.128 + 32 FFMA2, 2 acc chains ----
        const ulonglong2* m2 = (const ulonglong2*)slot;
        u64 acc0 = 0ULL, acc1 = 0ULL;
        #pragma unroll
        for (int jj = 0; jj < 16; jj++) {
            ulonglong2 v = m2[jj];
            acc0 = ffma2(v.x, w[2*jj],     acc0);
            acc1 = ffma2(v.y, w[2*jj + 1], acc1);
        }
        float x0, y0, x1, y1;
        unpack_f2(acc0, x0, y0);
        unpack_f2(acc1, x1, y1);
        float z = ((x0 + x1) + (y0 + y1)) * rc;

        out[(size_t)t * TOKEN_OUT + out_off] = fast_tanh(z);
    }
}

extern "C" void kernel_launch(void* const* d_in, const int* in_sizes, int n_in,
                              void* d_out, int out_size) {
    const int*   idx = (const int*)d_in[0];   // [B,N,K] int32
    const float* win = (const float*)d_in[1]; // [B,N,K,D_IN] f32
    const float* W   = (const float*)d_in[2]; // [C,D_OUT,D_IN] f32
    float* out = (float*)d_out;               // [B,N,C,D_OUT] f32

    const int total = in_sizes[0] / KNB;      // B*N tokens

    int sms = 148, dev = 0;
    cudaGetDevice(&dev);
    cudaDeviceGetAttribute(&sms, cudaDevAttrMultiProcessorCount, dev);
    int grid = (sms < total) ? sms : total;

    ordered_gcn_kernel<<<grid, NTHR>>>(idx, win, W, out, total);
}

// round 7
// speedup vs baseline: 3.2495x; 3.2495x over previous
#include <cuda_runtime.h>

// Ordered_GCN: B=64, N=207, K=32, C=8, D_IN=64, D_OUT=64, tokens = 13248.
// R6 = R3 skeleton (persistent CTA, cp.async double-buffered 8-token chunks,
// warp-local per-token processing) + intra-warp software pipelining:
//   - mean slot double-buffered (parity per token): GEMV of token j overlaps
//     scatter of token j+1 (FMA pipe vs MIO pipe), 1 __syncwarp per token
//   - GEMV smem reads via LDS.128 (16 loads / token / thread)
//   - per-warp token-order rotation inside chunk de-phases crossbar bursts

#define KNB   32
#define DIN   64
#define NTHR  512
#define CHUNK 8
#define TOKEN_IN  2048   // floats per token (32*64)
#define TOKEN_OUT 512    // floats per token (8*64)

#define WIN_FLOATS (2 * CHUNK * TOKEN_IN)   // 128KB
#define IDX_INTS   (2 * CHUNK * KNB)        // 2KB
#define STAGE_U64S (16 * 2 * 32)            // 16 warps x 2 slots x 32 pairs = 8KB
#define SMEM_BYTES (WIN_FLOATS * 4 + IDX_INTS * 4 + STAGE_U64S * 8)

typedef unsigned long long u64;

__device__ __forceinline__ u64 ffma2(u64 a, u64 b, u64 c) {
    u64 d;
    asm("fma.rn.f32x2 %0, %1, %2, %3;" : "=l"(d) : "l"(a), "l"(b), "l"(c));
    return d;
}
__device__ __forceinline__ u64 pack_f2(float x, float y) {
    u64 r; asm("mov.b64 %0, {%1, %2};" : "=l"(r) : "f"(x), "f"(y)); return r;
}
__device__ __forceinline__ void unpack_f2(u64 v, float& x, float& y) {
    asm("mov.b64 {%0, %1}, %2;" : "=f"(x), "=f"(y) : "l"(v));
}
__device__ __forceinline__ void cp_async16(void* smem, const void* gmem) {
    unsigned saddr = (unsigned)__cvta_generic_to_shared(smem);
    asm volatile("cp.async.cg.shared.global [%0], [%1], 16;" :: "r"(saddr), "l"(gmem));
}
__device__ __forceinline__ float fast_tanh(float z) {
    // 1 - 2/(e^{2z}+1): ~1e-7 abs err, saturates correctly
    float e = __expf(2.0f * z);
    return 1.0f - __fdividef(2.0f, e + 1.0f);
}

__global__ void __launch_bounds__(NTHR, 1)
ordered_gcn_kernel(const int* __restrict__ idx,
                   const float* __restrict__ win,
                   const float* __restrict__ W,
                   float* __restrict__ out,
                   int total, int ngroups)
{
    extern __shared__ float smem[];
    float* win_s = smem;                        // [2][CHUNK][2048]
    int*   idx_s = (int*)(smem + WIN_FLOATS);   // [2][CHUNK][32]
    u64*   stage = (u64*)(idx_s + IDX_INTS);    // [16 warps][2][32]

    const int tid  = threadIdx.x;
    const int lane = tid & 31;
    const int warp = tid >> 5;
    const int c    = warp >> 1;                 // class (warp-uniform)
    const int o    = ((warp & 1) << 5) | lane;  // output column 0..63

    // ---- W[c][o][0:64] register-resident as 32 packed f32x2 ----
    u64 w[32];
    {
        const float4* gw = (const float4*)(W + ((c * DIN + o) * DIN));
        #pragma unroll
        for (int j = 0; j < 16; j++) {
            float4 v = gw[j];
            w[2*j]   = pack_f2(v.x, v.y);
            w[2*j+1] = pack_f2(v.z, v.w);
        }
    }

    const int grid = gridDim.x;
    const int bid  = blockIdx.x;

    auto issue_group = [&](int g, int b) {
        if (g < ngroups) {
            int base = g * CHUNK;
            float* wdst = win_s + b * (CHUNK * TOKEN_IN);
            #pragma unroll
            for (int j = 0; j < CHUNK; j++) {
                int tok = base + j;
                if (tok < total)
                    cp_async16(wdst + j * TOKEN_IN + tid * 4,
                               win + (size_t)tok * TOKEN_IN + tid * 4);
            }
            if (tid < 64) {
                int j = tid >> 3, sl = (tid & 7) * 4;
                int tok = base + j;
                if (tok < total)
                    cp_async16(idx_s + b * (CHUNK * KNB) + j * KNB + sl,
                               idx + (size_t)tok * KNB + sl);
            }
        }
        asm volatile("cp.async.commit_group;");
    };

    issue_group(bid, 0);
    issue_group(bid + grid, 1);

    u64* slot = stage + warp * 64;              // two 32-pair buffers
    const int jrot = warp & (CHUNK - 1);        // per-warp rotation
    const size_t ocol = (size_t)(c << 6) + o;

    int it = 0;
    for (int g = bid; g < ngroups; g += grid, ++it) {
        asm volatile("cp.async.wait_group 1;");
        __syncthreads();

        const int buf  = it & 1;
        const int base = g * CHUNK;
        const float* wbuf = win_s + buf * (CHUNK * TOKEN_IN);
        const int*   ibuf = idx_s + buf * (CHUNK * KNB);

        // ---- prologue: scatter first token (rotated) into slot 0 ----
        float rc_prev;
        int   j_prev = jrot;
        {
            const int my = ibuf[j_prev * KNB + lane];
            unsigned mask = __ballot_sync(0xffffffffu, my == c);
            const int cnt = __popc(mask);
            rc_prev = __fdividef(1.0f, (float)(cnt > 0 ? cnt : 1));
            const float2* rows = (const float2*)(wbuf + j_prev * TOKEN_IN);
            float s0 = 0.0f, s1 = 0.0f;
            unsigned m = mask;
            while (m) {
                int k = __ffs(m) - 1; m &= m - 1;
                float2 v = rows[k * 32 + lane];
                s0 += v.x; s1 += v.y;
            }
            slot[lane] = pack_f2(s0, s1);
            __syncwarp();
        }

        // ---- pipelined: GEMV token i-1 overlaps scatter token i ----
        #pragma unroll
        for (int i = 1; i <= CHUNK; i++) {
            const int p = (i - 1) & 1;

            // scatter token i (independent of GEMV below -> ILP)
            float s0 = 0.0f, s1 = 0.0f, rc_next = 1.0f;
            int j_next = 0;
            if (i < CHUNK) {
                j_next = (jrot + i) & (CHUNK - 1);
                const int my = ibuf[j_next * KNB + lane];
                unsigned mask = __ballot_sync(0xffffffffu, my == c);
                const int cnt = __popc(mask);
                rc_next = __fdividef(1.0f, (float)(cnt > 0 ? cnt : 1));
                const float2* rows = (const float2*)(wbuf + j_next * TOKEN_IN);
                unsigned m = mask;
                while (m) {
                    int k = __ffs(m) - 1; m &= m - 1;
                    float2 v = rows[k * 32 + lane];
                    s0 += v.x; s1 += v.y;
                }
            }

            // GEMV on slot[p]: 16 LDS.128 + 32 FFMA2 (2 chains)
            const ulonglong2* m2 = (const ulonglong2*)(slot + p * 32);
            u64 acc0 = 0ULL, acc1 = 0ULL;
            #pragma unroll
            for (int jj = 0; jj < 16; jj++) {
                ulonglong2 v = m2[jj];
                acc0 = ffma2(v.x, w[2*jj],     acc0);
                acc1 = ffma2(v.y, w[2*jj + 1], acc1);
            }

            // publish next token's sums, then finish current token
            if (i < CHUNK) slot[(p ^ 1) * 32 + lane] = pack_f2(s0, s1);
            __syncwarp();

            float x0, y0, x1, y1;
            unpack_f2(acc0, x0, y0);
            unpack_f2(acc1, x1, y1);
            float z = ((x0 + x1) + (y0 + y1)) * rc_prev;
            const int tok = base + j_prev;
            if (tok < total)
                out[(size_t)tok * TOKEN_OUT + ocol] = fast_tanh(z);

            rc_prev = rc_next;
            j_prev  = j_next;
        }

        __syncthreads();                  // all warps done with buf
        issue_group(g + 2 * grid, buf);   // refill consumed buffer
    }
}

extern "C" void kernel_launch(void* const* d_in, const int* in_sizes, int n_in,
                              void* d_out, int out_size) {
    const int*   idx = (const int*)d_in[0];   // [B,N,K] int32
    const float* win = (const float*)d_in[1]; // [B,N,K,D_IN] f32
    const float* W   = (const float*)d_in[2]; // [C,D_OUT,D_IN] f32
    float* out = (float*)d_out;               // [B,N,C,D_OUT] f32

    const int total   = in_sizes[0] / KNB;
    const int ngroups = (total + CHUNK - 1) / CHUNK;

    static int smem_set = 0;
    if (!smem_set) {
        cudaFuncSetAttribute(ordered_gcn_kernel,
                             cudaFuncAttributeMaxDynamicSharedMemorySize,
                             SMEM_BYTES);
        smem_set = 1;
    }

    int sms = 148, dev = 0;
    cudaGetDevice(&dev);
    cudaDeviceGetAttribute(&sms, cudaDevAttrMultiProcessorCount, dev);
    int grid = (sms < ngroups) ? sms : ngroups;

    ordered_gcn_kernel<<<grid, NTHR, SMEM_BYTES>>>(idx, win, W, out, total, ngroups);
}

// round 9
// speedup vs baseline: 4.7922x; 1.4748x over previous
#include <cuda_runtime.h>
#include <cuda_fp16.h>
#include <cstdint>

// Ordered_GCN: B=64, N=207, K=32, C=8, D_IN=64, D_OUT=64, tokens = 13248.
// R8: tensor cores via portable mma.sync (HMMA) -- tcgen05 not emittable on
// this toolchain (PTX target sm_103 without 'a').
//  - batch TB=16 tokens; A[8cls*16tok][64] fp16 means in smem (SW128, 2 bufs)
//  - W fp16 in smem (8 * 64x64, SW128), converted once
//  - 32 warps: MMA role (class, n-quarter16): m16n8k16, 4 k-steps, 2 n-tiles
//  - scatter role (class, token-in-chunk): ballot + ~4 LDS.64 rows + 1 STS
//  - input ring-3 cp.async (4-token chunks); 5 __syncthreads per 16 tokens
// total = 13248 = 828 * 16 exactly -> no tail guards on the batch path.

#define KNB   32
#define NTHR  1024
#define CHUNK 4
#define TB    16
#define RING  3
#define TOKEN_IN  2048
#define TOKEN_OUT 512

#define WIN_BYTES (RING * CHUNK * 8192)        // 98304
#define OFF_A     WIN_BYTES                    // 98304 (1024-aligned)
#define A_BUF     16384                        // 128 rows x 128B
#define OFF_W     (OFF_A + 2 * A_BUF)          // 131072
#define OFF_IDX   (OFF_W + 65536)              // 196608
#define IDX_BYTES (RING * CHUNK * KNB * 4)     // 1536
#define SMEM_BYTES (OFF_IDX + IDX_BYTES + 1024)

#define SW128(o) ((o) ^ (((o) >> 3) & 0x70))

__device__ __forceinline__ void cp_async16(void* smem, const void* gmem) {
    unsigned saddr = (unsigned)__cvta_generic_to_shared(smem);
    asm volatile("cp.async.cg.shared.global [%0], [%1], 16;" :: "r"(saddr), "l"(gmem));
}
__device__ __forceinline__ float fast_tanh(float z) {
    float e = __expf(2.0f * z);
    return 1.0f - __fdividef(2.0f, e + 1.0f);
}

__global__ void __launch_bounds__(NTHR, 1)
ordered_gcn_kernel(const int* __restrict__ idx,
                   const float* __restrict__ win,
                   const float* __restrict__ W,
                   float* __restrict__ out,
                   int total, int nbatch)
{
    extern __shared__ char raw[];
    char* base = (char*)(((uintptr_t)raw + 1023) & ~(uintptr_t)1023);
    const uint32_t sb = (uint32_t)__cvta_generic_to_shared(base);
    float* win_s = (float*)base;                 // [RING][CHUNK][2048] f32
    char*  A_s   = base + OFF_A;                 // [2][128][128B] fp16
    char*  W_s   = base + OFF_W;                 // [8][64][128B] fp16
    int*   idx_s = (int*)(base + OFF_IDX);       // [RING][CHUNK][32]

    const int tid  = threadIdx.x;
    const int lane = tid & 31;
    const int w    = tid >> 5;
    const int grid = gridDim.x;

    // ---- convert W fp32 gmem -> fp16 smem (SW128 rows of 128B) ----
    for (int i = tid; i < 16384; i += NTHR) {        // fp16x2 pairs
        int c = i >> 11, o = (i >> 5) & 63, dp = i & 31;
        float2 v = ((const float2*)W)[i];
        *(__half2*)(W_s + c * 8192 + SW128(o * 128 + dp * 4)) =
            __floats2half2_rn(v.x, v.y);
    }

    auto issue_chunk = [&](int seq) {
        int bb = blockIdx.x + (seq >> 2) * grid;
        if (bb < nbatch) {
            int cb = bb * TB + (seq & 3) * CHUNK;
            char* dst = (char*)win_s + (size_t)(seq % RING) * CHUNK * 8192;
            #pragma unroll
            for (int p = 0; p < 2; p++) {
                int flat = tid + p * NTHR;           // 0..2047
                int j = flat >> 9, sl = flat & 511;
                cp_async16(dst + j * 8192 + sl * 16,
                           (const char*)win + (size_t)(cb + j) * 8192 + sl * 16);
            }
            if (tid < 32) {
                int j = tid >> 3, s4 = (tid & 7) * 4;
                cp_async16(idx_s + (seq % RING) * CHUNK * KNB + j * KNB + s4,
                           idx + (size_t)(cb + j) * KNB + s4);
            }
        }
        asm volatile("cp.async.commit_group;");
    };
    issue_chunk(0);
    issue_chunk(1);

    // roles (both use the same decomposition of 32 warps)
    const int cs = w & 7, js = w >> 3;   // scatter: class cs, token js in chunk
    const int cm = w & 7, nq = w >> 3;   // mma: class cm, n-quarter nq (16 cols)

    int bi = 0;
    for (int b = blockIdx.x; b < nbatch; b += grid, ++bi) {
        const int ab = bi & 1;
        char* Ab = A_s + ab * A_BUF;

        // ---- 4 chunks: scatter means into A[ab] ----
        #pragma unroll
        for (int q = 0; q < 4; q++) {
            const int seq = bi * 4 + q;
            asm volatile("cp.async.wait_group 1;" ::: "memory");
            __syncthreads();

            const int slot = seq % RING;
            const int* ib = idx_s + (slot * CHUNK + js) * KNB;
            int my = ib[lane];
            unsigned mask = __ballot_sync(0xffffffffu, my == cs);
            int cnt = __popc(mask);
            float rc = __fdividef(1.0f, (float)(cnt > 0 ? cnt : 1));
            const float2* rows =
                (const float2*)(win_s + (size_t)(slot * CHUNK + js) * TOKEN_IN);
            float s0 = 0.0f, s1 = 0.0f;
            unsigned m = mask;
            while (m) {
                int k = __ffs(m) - 1;
                m &= m - 1;
                float2 v = rows[k * 32 + lane];
                s0 += v.x; s1 += v.y;
            }
            int row = cs * 16 + q * CHUNK + js;      // [class][token-in-batch]
            *(__half2*)(Ab + SW128(row * 128 + lane * 4)) =
                __floats2half2_rn(s0 * rc, s1 * rc);

            issue_chunk(seq + 2);
        }
        __syncthreads();                 // A[ab] complete (W_s too, 1st batch)

        // ---- MMA: M=16 tokens, N=16 (quarter), K=64 ----
        const uint32_t abase = sb + OFF_A + ab * A_BUF;
        const uint32_t wbase = sb + OFF_W + cm * 8192;
        float acc[2][4] = {};
        #pragma unroll
        for (int kk = 0; kk < 4; kk++) {
            uint32_t a0, a1, a2, a3;
            {
                unsigned row = cm * 16 + (lane & 15);
                unsigned off = SW128(row * 128 + kk * 32 + ((lane >> 4) << 4));
                asm volatile(
                    "ldmatrix.sync.aligned.m8n8.x4.shared.b16 {%0,%1,%2,%3}, [%4];"
                    : "=r"(a0), "=r"(a1), "=r"(a2), "=r"(a3) : "r"(abase + off));
            }
            #pragma unroll
            for (int nt = 0; nt < 2; nt++) {
                uint32_t b0, b1;
                // B stored [n][k] row-major == col-major KxN -> NON-trans load
                unsigned nrow = nq * 16 + nt * 8 + (lane & 7);
                unsigned off  = SW128(nrow * 128 + kk * 32 + ((lane >> 3) & 1) * 16);
                asm volatile(
                    "ldmatrix.sync.aligned.m8n8.x2.shared.b16 {%0,%1}, [%2];"
                    : "=r"(b0), "=r"(b1) : "r"(wbase + off));
                asm volatile(
                    "mma.sync.aligned.m16n8k16.row.col.f32.f16.f16.f32 "
                    "{%0,%1,%2,%3}, {%4,%5,%6,%7}, {%8,%9}, {%0,%1,%2,%3};"
                    : "+f"(acc[nt][0]), "+f"(acc[nt][1]),
                      "+f"(acc[nt][2]), "+f"(acc[nt][3])
                    : "r"(a0), "r"(a1), "r"(a2), "r"(a3), "r"(b0), "r"(b1));
            }
        }

        // ---- epilogue: tanh + store (C frag: rows lane>>2, +8; cols 2*(lane&3)) ----
        const int tb = b * TB;
        #pragma unroll
        for (int nt = 0; nt < 2; nt++) {
            int col = cm * 64 + nq * 16 + nt * 8 + (lane & 3) * 2;
            int r0 = tb + (lane >> 2), r1 = r0 + 8;
            float2 v0 = { fast_tanh(acc[nt][0]), fast_tanh(acc[nt][1]) };
            float2 v1 = { fast_tanh(acc[nt][2]), fast_tanh(acc[nt][3]) };
            *(float2*)(out + (size_t)r0 * TOKEN_OUT + col) = v0;
            *(float2*)(out + (size_t)r1 * TOKEN_OUT + col) = v1;
        }
    }
}

extern "C" void kernel_launch(void* const* d_in, const int* in_sizes, int n_in,
                              void* d_out, int out_size) {
    const int*   idx = (const int*)d_in[0];   // [B,N,K] int32
    const float* win = (const float*)d_in[1]; // [B,N,K,D_IN] f32
    const float* W   = (const float*)d_in[2]; // [C,D_OUT,D_IN] f32
    float* out = (float*)d_out;               // [B,N,C,D_OUT] f32

    const int total  = in_sizes[0] / KNB;     // 13248
    const int nbatch = total / TB;            // 828 (exact)

    static int smem_set = 0;
    if (!smem_set) {
        cudaFuncSetAttribute(ordered_gcn_kernel,
                             cudaFuncAttributeMaxDynamicSharedMemorySize,
                             SMEM_BYTES);
        smem_set = 1;
    }

    int sms = 148, dev = 0;
    cudaGetDevice(&dev);
    cudaDeviceGetAttribute(&sms, cudaDevAttrMultiProcessorCount, dev);
    int grid = (sms < nbatch) ? sms : nbatch;

    ordered_gcn_kernel<<<grid, NTHR, SMEM_BYTES>>>(idx, win, W, out, total, nbatch);
}

// round 10
// speedup vs baseline: 5.0587x; 1.0556x over previous
#include <cuda_runtime.h>
#include <cuda_fp16.h>
#include <cstdint>

// Ordered_GCN: B=64, N=207, K=32, C=8, D_IN=64, D_OUT=64, tokens = 13248.
// R9 = R8 (HMMA mma.sync tensor-core GEMM, fp16 means/weights, fp32 accum)
// with input staging switched from per-thread cp.async (256 warp-ops/batch)
// to single-thread cp.async.bulk (2 ops/batch) + mbarrier completion.
//  - batch TB=16 tokens; A[8cls*16tok][64] fp16 means in smem (SW128, 2 bufs)
//  - W fp16 in smem (8 * 64x64, SW128), converted once
//  - 32 warps: scatter role (class, token-in-chunk) / MMA role (class, n-q16)
//  - ring-3 input slots (4 tokens = 32KB each), bulk-copied, parity-tracked
// total = 13248 = 828 * 16 exactly -> no tail guards on the batch path.

#define KNB   32
#define NTHR  1024
#define CHUNK 4
#define TB    16
#define RING  3
#define TOKEN_IN  2048
#define TOKEN_OUT 512

#define WIN_SLOT  32768                         // 4 tokens * 8KB
#define OFF_A     (RING * WIN_SLOT)             // 98304
#define A_BUF     16384                         // 128 rows x 128B
#define OFF_W     (OFF_A + 2 * A_BUF)           // 131072
#define OFF_IDX   (OFF_W + 65536)               // 196608 (16B-aligned slots)
#define IDX_SLOT  512                           // 4 tokens * 128B
#define OFF_MBAR  (OFF_IDX + RING * IDX_SLOT)   // 198144
#define SMEM_BYTES (OFF_MBAR + 64 + 1024)

#define SW128(o) ((o) ^ (((o) >> 3) & 0x70))

__device__ __forceinline__ float fast_tanh(float z) {
    float e = __expf(2.0f * z);
    return 1.0f - __fdividef(2.0f, e + 1.0f);
}

#define MBAR_INIT(addr, cnt) \
    asm volatile("mbarrier.init.shared.b64 [%0], %1;" :: "r"(addr), "r"(cnt) : "memory")
#define MBAR_WAIT(addr, par) do {                                              \
    uint32_t _m = (addr), _p = (par), _d;                                      \
    asm volatile("{\n\t.reg .pred p;\n\t"                                      \
        "mbarrier.try_wait.parity.acquire.cta.shared::cta.b64 p, [%1], %2;\n\t"\
        "selp.b32 %0, 1, 0, p;\n\t}" : "=r"(_d) : "r"(_m), "r"(_p) : "memory");\
    if (!_d) {                                                                 \
        asm volatile("{\n\t.reg .pred P1;\n\t"                                 \
        "WL%=:\n\t"                                                            \
        "mbarrier.try_wait.parity.acquire.cta.shared::cta.b64 P1, [%0], %1, 0x989680;\n\t" \
        "@P1 bra.uni WD%=;\n\t"                                                \
        "bra.uni WL%=;\n\t"                                                    \
        "WD%=:\n\t}" :: "r"(_m), "r"(_p) : "memory");                          \
    }                                                                          \
} while (0)

__global__ void __launch_bounds__(NTHR, 1)
ordered_gcn_kernel(const int* __restrict__ idx,
                   const float* __restrict__ win,
                   const float* __restrict__ W,
                   float* __restrict__ out,
                   int total, int nbatch)
{
    extern __shared__ char raw[];
    char* base = (char*)(((uintptr_t)raw + 1023) & ~(uintptr_t)1023);
    const uint32_t sb = (uint32_t)__cvta_generic_to_shared(base);
    char* W_s = base + OFF_W;

    const int tid  = threadIdx.x;
    const int lane = tid & 31;
    const int w    = tid >> 5;
    const int grid = gridDim.x;

    // ---- one-thread bulk staging of a 4-token chunk into ring slot ----
    auto issue_chunk = [&](int seq) {
        int bb = blockIdx.x + (seq >> 2) * grid;
        if (bb >= nbatch) return;
        int slot = seq % RING;
        uint32_t mbar = sb + OFF_MBAR + slot * 8;
        size_t cb = (size_t)bb * TB + (seq & 3) * CHUNK;
        asm volatile("mbarrier.arrive.expect_tx.shared.b64 _, [%0], %1;"
                     :: "r"(mbar), "r"(33280u) : "memory");
        asm volatile(
            "cp.async.bulk.shared::cta.global.mbarrier::complete_tx::bytes "
            "[%0], [%1], %2, [%3];"
            :: "r"(sb + slot * WIN_SLOT), "l"((const char*)win + cb * 8192),
               "r"((uint32_t)WIN_SLOT), "r"(mbar) : "memory");
        asm volatile(
            "cp.async.bulk.shared::cta.global.mbarrier::complete_tx::bytes "
            "[%0], [%1], %2, [%3];"
            :: "r"(sb + OFF_IDX + slot * IDX_SLOT), "l"((const char*)idx + cb * 128),
               "r"((uint32_t)IDX_SLOT), "r"(mbar) : "memory");
    };

    if (tid == 0) {
        #pragma unroll
        for (int s = 0; s < RING; s++) MBAR_INIT(sb + OFF_MBAR + s * 8, 1);
    }
    __syncthreads();                 // mbar init visible before any wait/issue
    if (tid == 0) { issue_chunk(0); issue_chunk(1); }

    // ---- convert W fp32 gmem -> fp16 smem (SW128 rows of 128B) ----
    for (int i = tid; i < 16384; i += NTHR) {        // fp16x2 pairs
        int c = i >> 11, o = (i >> 5) & 63, dp = i & 31;
        float2 v = ((const float2*)W)[i];
        *(__half2*)(W_s + c * 8192 + SW128(o * 128 + dp * 4)) =
            __floats2half2_rn(v.x, v.y);
    }

    // roles (both decompose the 32 warps the same way)
    const int cs = w & 7, js = w >> 3;   // scatter: class cs, token js in chunk
    const int cm = w & 7, nq = w >> 3;   // mma: class cm, n-quarter nq

    int bi = 0;
    for (int b = blockIdx.x; b < nbatch; b += grid, ++bi) {
        const int ab = bi & 1;
        char* Ab = base + OFF_A + ab * A_BUF;

        // ---- 4 chunks: scatter class-means into A[ab] ----
        #pragma unroll
        for (int q = 0; q < 4; q++) {
            const int seq  = bi * 4 + q;
            const int slot = seq % RING;
            MBAR_WAIT(sb + OFF_MBAR + slot * 8, (uint32_t)((seq / RING) & 1));
            __syncthreads();   // all readers of slot (seq-1)%3 are done too

            const int* ib = (const int*)(base + OFF_IDX + slot * IDX_SLOT) + js * KNB;
            int my = ib[lane];
            unsigned mask = __ballot_sync(0xffffffffu, my == cs);
            int cnt = __popc(mask);
            float rc = __fdividef(1.0f, (float)(cnt > 0 ? cnt : 1));
            const float2* rows =
                (const float2*)(base + slot * WIN_SLOT + js * 8192);
            float s0 = 0.0f, s1 = 0.0f;
            unsigned m = mask;
            while (m) {
                int k = __ffs(m) - 1;
                m &= m - 1;
                float2 v = rows[k * 32 + lane];
                s0 += v.x; s1 += v.y;
            }
            int row = cs * 16 + q * CHUNK + js;      // [class][token-in-batch]
            *(__half2*)(Ab + SW128(row * 128 + lane * 4)) =
                __floats2half2_rn(s0 * rc, s1 * rc);

            if (tid == 0) issue_chunk(seq + 2);      // refill slot (seq-1)%3
        }
        __syncthreads();                 // A[ab] complete (W_s too, 1st batch)

        // ---- MMA: M=16 tokens, N=16 (quarter), K=64, 4 k-steps ----
        const uint32_t abase = sb + OFF_A + ab * A_BUF;
        const uint32_t wbase = sb + OFF_W + cm * 8192;
        float acc[2][4] = {};
        #pragma unroll
        for (int kk = 0; kk < 4; kk++) {
            uint32_t a0, a1, a2, a3;
            {
                unsigned row = cm * 16 + (lane & 15);
                unsigned off = SW128(row * 128 + kk * 32 + ((lane >> 4) << 4));
                asm volatile(
                    "ldmatrix.sync.aligned.m8n8.x4.shared.b16 {%0,%1,%2,%3}, [%4];"
                    : "=r"(a0), "=r"(a1), "=r"(a2), "=r"(a3) : "r"(abase + off));
            }
            #pragma unroll
            for (int nt = 0; nt < 2; nt++) {
                uint32_t b0, b1;
                // W stored [n][k] row-major == col-major KxN -> NON-trans load
                unsigned nrow = nq * 16 + nt * 8 + (lane & 7);
                unsigned off  = SW128(nrow * 128 + kk * 32 + ((lane >> 3) & 1) * 16);
                asm volatile(
                    "ldmatrix.sync.aligned.m8n8.x2.shared.b16 {%0,%1}, [%2];"
                    : "=r"(b0), "=r"(b1) : "r"(wbase + off));
                asm volatile(
                    "mma.sync.aligned.m16n8k16.row.col.f32.f16.f16.f32 "
                    "{%0,%1,%2,%3}, {%4,%5,%6,%7}, {%8,%9}, {%0,%1,%2,%3};"
                    : "+f"(acc[nt][0]), "+f"(acc[nt][1]),
                      "+f"(acc[nt][2]), "+f"(acc[nt][3])
                    : "r"(a0), "r"(a1), "r"(a2), "r"(a3), "r"(b0), "r"(b1));
            }
        }

        // ---- epilogue: tanh + store (C frag rows lane>>2,+8; cols 2*(lane&3)) ----
        const int tb = b * TB;
        #pragma unroll
        for (int nt = 0; nt < 2; nt++) {
            int col = cm * 64 + nq * 16 + nt * 8 + (lane & 3) * 2;
            int r0 = tb + (lane >> 2), r1 = r0 + 8;
            float2 v0 = { fast_tanh(acc[nt][0]), fast_tanh(acc[nt][1]) };
            float2 v1 = { fast_tanh(acc[nt][2]), fast_tanh(acc[nt][3]) };
            *(float2*)(out + (size_t)r0 * TOKEN_OUT + col) = v0;
            *(float2*)(out + (size_t)r1 * TOKEN_OUT + col) = v1;
        }
    }
}

extern "C" void kernel_launch(void* const* d_in, const int* in_sizes, int n_in,
                              void* d_out, int out_size) {
    const int*   idx = (const int*)d_in[0];   // [B,N,K] int32
    const float* win = (const float*)d_in[1]; // [B,N,K,D_IN] f32
    const float* W   = (const float*)d_in[2]; // [C,D_OUT,D_IN] f32
    float* out = (float*)d_out;               // [B,N,C,D_OUT] f32

    const int total  = in_sizes[0] / KNB;     // 13248
    const int nbatch = total / TB;            // 828 (exact)

    static int smem_set = 0;
    if (!smem_set) {
        cudaFuncSetAttribute(ordered_gcn_kernel,
                             cudaFuncAttributeMaxDynamicSharedMemorySize,
                             SMEM_BYTES);
        smem_set = 1;
    }

    int sms = 148, dev = 0;
    cudaGetDevice(&dev);
    cudaDeviceGetAttribute(&sms, cudaDevAttrMultiProcessorCount, dev);
    int grid = (sms < nbatch) ? sms : nbatch;

    ordered_gcn_kernel<<<grid, NTHR, SMEM_BYTES>>>(idx, win, W, out, total, nbatch);
}

// round 11
// speedup vs baseline: 5.2831x; 1.0444x over previous
#include <cuda_runtime.h>
#include <cuda_fp16.h>
#include <cstdint>

// Ordered_GCN: B=64, N=207, K=32, C=8, D_IN=64, D_OUT=64, tokens = 13248.
// R10 = R9 (HMMA mma.sync GEMM, fp16 means/weights, fp32 accum, cp.async.bulk
// staging) with a deeper copy pipeline:
//  - RING=4 input slots (4 tokens = 32KB each), issue depth 3 (97.5KB in flight)
//  - SINGLE A buffer (safe: next batch's A writes happen after chunk-0 barrier,
//    which warps reach only after finishing prior batch's ldmatrix reads)
// total = 13248 = 828 * 16 exactly -> no tail guards on the batch path.

#define KNB   32
#define NTHR  1024
#define CHUNK 4
#define TB    16
#define RING  4
#define DEPTH 3
#define TOKEN_IN  2048
#define TOKEN_OUT 512

#define WIN_SLOT  32768                         // 4 tokens * 8KB
#define OFF_A     (RING * WIN_SLOT)             // 131072
#define A_BUF     16384                         // 128 rows x 128B
#define OFF_W     (OFF_A + A_BUF)               // 147456
#define OFF_IDX   (OFF_W + 65536)               // 212992 (16B-aligned slots)
#define IDX_SLOT  512                           // 4 tokens * 128B
#define OFF_MBAR  (OFF_IDX + RING * IDX_SLOT)   // 215040
#define SMEM_BYTES (OFF_MBAR + 64 + 1024)       // ~211KB

#define SW128(o) ((o) ^ (((o) >> 3) & 0x70))

__device__ __forceinline__ float fast_tanh(float z) {
    float e = __expf(2.0f * z);
    return 1.0f - __fdividef(2.0f, e + 1.0f);
}

#define MBAR_INIT(addr, cnt) \
    asm volatile("mbarrier.init.shared.b64 [%0], %1;" :: "r"(addr), "r"(cnt) : "memory")
#define MBAR_WAIT(addr, par) do {                                              \
    uint32_t _m = (addr), _p = (par), _d;                                      \
    asm volatile("{\n\t.reg .pred p;\n\t"                                      \
        "mbarrier.try_wait.parity.acquire.cta.shared::cta.b64 p, [%1], %2;\n\t"\
        "selp.b32 %0, 1, 0, p;\n\t}" : "=r"(_d) : "r"(_m), "r"(_p) : "memory");\
    if (!_d) {                                                                 \
        asm volatile("{\n\t.reg .pred P1;\n\t"                                 \
        "WL%=:\n\t"                                                            \
        "mbarrier.try_wait.parity.acquire.cta.shared::cta.b64 P1, [%0], %1, 0x989680;\n\t" \
        "@P1 bra.uni WD%=;\n\t"                                                \
        "bra.uni WL%=;\n\t"                                                    \
        "WD%=:\n\t}" :: "r"(_m), "r"(_p) : "memory");                          \
    }                                                                          \
} while (0)

__global__ void __launch_bounds__(NTHR, 1)
ordered_gcn_kernel(const int* __restrict__ idx,
                   const float* __restrict__ win,
                   const float* __restrict__ W,
                   float* __restrict__ out,
                   int total, int nbatch)
{
    extern __shared__ char raw[];
    char* base = (char*)(((uintptr_t)raw + 1023) & ~(uintptr_t)1023);
    const uint32_t sb = (uint32_t)__cvta_generic_to_shared(base);
    char* W_s = base + OFF_W;

    const int tid  = threadIdx.x;
    const int lane = tid & 31;
    const int w    = tid >> 5;
    const int grid = gridDim.x;

    // ---- one-thread bulk staging of a 4-token chunk into a ring slot ----
    auto issue_chunk = [&](int seq) {
        int bb = blockIdx.x + (seq >> 2) * grid;
        if (bb >= nbatch) return;
        int slot = seq & (RING - 1);
        uint32_t mbar = sb + OFF_MBAR + slot * 8;
        size_t cb = (size_t)bb * TB + (seq & 3) * CHUNK;
        asm volatile("mbarrier.arrive.expect_tx.shared.b64 _, [%0], %1;"
                     :: "r"(mbar), "r"(33280u) : "memory");
        asm volatile(
            "cp.async.bulk.shared::cta.global.mbarrier::complete_tx::bytes "
            "[%0], [%1], %2, [%3];"
            :: "r"(sb + slot * WIN_SLOT), "l"((const char*)win + cb * 8192),
               "r"((uint32_t)WIN_SLOT), "r"(mbar) : "memory");
        asm volatile(
            "cp.async.bulk.shared::cta.global.mbarrier::complete_tx::bytes "
            "[%0], [%1], %2, [%3];"
            :: "r"(sb + OFF_IDX + slot * IDX_SLOT), "l"((const char*)idx + cb * 128),
               "r"((uint32_t)IDX_SLOT), "r"(mbar) : "memory");
    };

    if (tid == 0) {
        #pragma unroll
        for (int s = 0; s < RING; s++) MBAR_INIT(sb + OFF_MBAR + s * 8, 1);
    }
    __syncthreads();                 // mbar init visible before any wait/issue
    if (tid == 0) {
        issue_chunk(0); issue_chunk(1); issue_chunk(2);
    }

    // ---- convert W fp32 gmem -> fp16 smem (SW128 rows of 128B) ----
    for (int i = tid; i < 16384; i += NTHR) {        // fp16x2 pairs
        int c = i >> 11, o = (i >> 5) & 63, dp = i & 31;
        float2 v = ((const float2*)W)[i];
        *(__half2*)(W_s + c * 8192 + SW128(o * 128 + dp * 4)) =
            __floats2half2_rn(v.x, v.y);
    }

    // roles (both decompose the 32 warps the same way)
    const int cs = w & 7, js = w >> 3;   // scatter: class cs, token js in chunk
    const int cm = w & 7, nq = w >> 3;   // mma: class cm, n-quarter nq

    char* A_s = base + OFF_A;
    const uint32_t abase = sb + OFF_A;
    const uint32_t wbase = sb + OFF_W + cm * 8192;

    int bi = 0;
    for (int b = blockIdx.x; b < nbatch; b += grid, ++bi) {
        // ---- 4 chunks: scatter class-means into A ----
        #pragma unroll
        for (int q = 0; q < 4; q++) {
            const int seq  = bi * 4 + q;
            const int slot = seq & (RING - 1);
            MBAR_WAIT(sb + OFF_MBAR + slot * 8, (uint32_t)((seq >> 2) & 1));
            __syncthreads();   // also: all readers of slot (seq-1)%RING done;
                               // and (q==0) all prior-batch A reads complete

            const int* ib = (const int*)(base + OFF_IDX + slot * IDX_SLOT) + js * KNB;
            int my = ib[lane];
            unsigned mask = __ballot_sync(0xffffffffu, my == cs);
            int cnt = __popc(mask);
            float rc = __fdividef(1.0f, (float)(cnt > 0 ? cnt : 1));
            const float2* rows =
                (const float2*)(base + slot * WIN_SLOT + js * 8192);
            float s0 = 0.0f, s1 = 0.0f;
            unsigned m = mask;
            while (m) {
                int k = __ffs(m) - 1;
                m &= m - 1;
                float2 v = rows[k * 32 + lane];
                s0 += v.x; s1 += v.y;
            }
            int row = cs * 16 + q * CHUNK + js;      // [class][token-in-batch]
            *(__half2*)(A_s + SW128(row * 128 + lane * 4)) =
                __floats2half2_rn(s0 * rc, s1 * rc);

            if (tid == 0) issue_chunk(seq + DEPTH);  // refill (readers done)
        }
        __syncthreads();                 // A complete (W_s too, 1st batch)

        // ---- MMA: M=16 tokens, N=16 (quarter), K=64, 4 k-steps ----
        float acc[2][4] = {};
        #pragma unroll
        for (int kk = 0; kk < 4; kk++) {
            uint32_t a0, a1, a2, a3;
            {
                unsigned row = cm * 16 + (lane & 15);
                unsigned off = SW128(row * 128 + kk * 32 + ((lane >> 4) << 4));
                asm volatile(
                    "ldmatrix.sync.aligned.m8n8.x4.shared.b16 {%0,%1,%2,%3}, [%4];"
                    : "=r"(a0), "=r"(a1), "=r"(a2), "=r"(a3) : "r"(abase + off));
            }
            #pragma unroll
            for (int nt = 0; nt < 2; nt++) {
                uint32_t b0, b1;
                // W stored [n][k] row-major == col-major KxN -> NON-trans load
                unsigned nrow = nq * 16 + nt * 8 + (lane & 7);
                unsigned off  = SW128(nrow * 128 + kk * 32 + ((lane >> 3) & 1) * 16);
                asm volatile(
                    "ldmatrix.sync.aligned.m8n8.x2.shared.b16 {%0,%1}, [%2];"
                    : "=r"(b0), "=r"(b1) : "r"(wbase + off));
                asm volatile(
                    "mma.sync.aligned.m16n8k16.row.col.f32.f16.f16.f32 "
                    "{%0,%1,%2,%3}, {%4,%5,%6,%7}, {%8,%9}, {%0,%1,%2,%3};"
                    : "+f"(acc[nt][0]), "+f"(acc[nt][1]),
                      "+f"(acc[nt][2]), "+f"(acc[nt][3])
                    : "r"(a0), "r"(a1), "r"(a2), "r"(a3), "r"(b0), "r"(b1));
            }
        }

        // ---- epilogue: tanh + store (C frag rows lane>>2,+8; cols 2*(lane&3)) ----
        const int tb = b * TB;
        #pragma unroll
        for (int nt = 0; nt < 2; nt++) {
            int col = cm * 64 + nq * 16 + nt * 8 + (lane & 3) * 2;
            int r0 = tb + (lane >> 2), r1 = r0 + 8;
            float2 v0 = { fast_tanh(acc[nt][0]), fast_tanh(acc[nt][1]) };
            float2 v1 = { fast_tanh(acc[nt][2]), fast_tanh(acc[nt][3]) };
            *(float2*)(out + (size_t)r0 * TOKEN_OUT + col) = v0;
            *(float2*)(out + (size_t)r1 * TOKEN_OUT + col) = v1;
        }
    }
}

extern "C" void kernel_launch(void* const* d_in, const int* in_sizes, int n_in,
                              void* d_out, int out_size) {
    const int*   idx = (const int*)d_in[0];   // [B,N,K] int32
    const float* win = (const float*)d_in[1]; // [B,N,K,D_IN] f32
    const float* W   = (const float*)d_in[2]; // [C,D_OUT,D_IN] f32
    float* out = (float*)d_out;               // [B,N,C,D_OUT] f32

    const int total  = in_sizes[0] / KNB;     // 13248
    const int nbatch = total / TB;            // 828 (exact)

    static int smem_set = 0;
    if (!smem_set) {
        cudaFuncSetAttribute(ordered_gcn_kernel,
                             cudaFuncAttributeMaxDynamicSharedMemorySize,
                             SMEM_BYTES);
        smem_set = 1;
    }

    int sms = 148, dev = 0;
    cudaGetDevice(&dev);
    cudaDeviceGetAttribute(&sms, cudaDevAttrMultiProcessorCount, dev);
    int grid = (sms < nbatch) ? sms : nbatch;

    ordered_gcn_kernel<<<grid, NTHR, SMEM_BYTES>>>(idx, win, W, out, total, nbatch);
}